// round 2
// baseline (speedup 1.0000x reference)
#include <cuda_runtime.h>
#include <math.h>

// ---------------- problem dims ----------------
#define Bb   8
#define Ss   2048
#define RR   (Bb*Ss)       // 16384 rows
#define DIN  1024
#define HH   2048
#define KK   256
#define DM   512
#define DOUT 1024
#define BANKN 4096

// ---------------- device scratch (static, allowed) ----------------
__device__ float    d_h[(size_t)RR*HH];        // 134 MB
__device__ float    d_logits[(size_t)RR*KK];   // 16.8 MB
__device__ int      d_a0[RR];
__device__ float    d_m0[RR];
__device__ unsigned d_keep[(size_t)RR*8];      // 256-bit keep masks
__device__ int      d_mode[RR];
__device__ float    d_knT[(size_t)DM*BANKN];   // normalized bank keys, transposed [DM,BANK]
__device__ float    d_qn[KK*DM];               // normalized M rows
__device__ float    d_scores[(size_t)KK*BANKN];// scores / attn (in place)
__device__ float    d_part[8*KK*DM];           // split-K partials
__device__ float    d_bankt[KK*DM];            // bank table
__device__ float    d_rn[KK*DM];               // rms-normed table
__device__ float    d_ytab[KK*DOUT];           // final per-mode output rows

// ---------------- packed f32x2 helpers ----------------
__device__ __forceinline__ unsigned long long pack2f(float lo, float hi){
    unsigned long long r; asm("mov.b64 %0, {%1,%2};" : "=l"(r) : "f"(lo), "f"(hi)); return r;
}
__device__ __forceinline__ void unpack2f(unsigned long long v, float& lo, float& hi){
    asm("mov.b64 {%0,%1}, %2;" : "=f"(lo), "=f"(hi) : "l"(v));
}
__device__ __forceinline__ void ffma2(unsigned long long& d, unsigned long long a, unsigned long long b){
    asm("fma.rn.f32x2 %0, %1, %2, %0;" : "+l"(d) : "l"(a), "l"(b));
}

// ---------------- 128x128x16 fp32 GEMM (dual-issue f32x2 inner loop) ----------------
// C[M,N] = alpha*(A[M,K] @ B[K,N]) + bias[N], optional relu.
// gridDim.z>1 => split-K: writes raw partials to C + z*M*N (no alpha/bias/relu).
__global__ void __launch_bounds__(256, 2) gemm128(
    const float* __restrict__ A, const float* __restrict__ B,
    const float* __restrict__ bias, float* __restrict__ C,
    int M, int N, int Kd, float alpha, int doRelu)
{
    __shared__ float As[16][128];
    __shared__ float Bs[16][128];
    const int tid = threadIdx.x;
    const int bx = blockIdx.x, by = blockIdx.y;
    const int nz = gridDim.z;
    const int Kper = Kd / nz;
    const int kBase = blockIdx.z * Kper;
    const bool partial = (nz > 1);
    if (partial) C += (size_t)blockIdx.z * (size_t)M * N;

    const int aRow = tid >> 2;            // 0..63
    const int aCol = (tid & 3) << 2;      // 0,4,8,12
    const int bRow = tid >> 5;            // 0..7
    const int bCol = (tid & 31) << 2;     // 0..124
    const int tx = tid & 15, ty = tid >> 4;

    unsigned long long acc[4][8];
#pragma unroll
    for (int i = 0; i < 4; i++)
#pragma unroll
        for (int j = 0; j < 8; j++) acc[i][j] = 0ull;

    const float* Abase = A + (size_t)(by*128)*Kd + kBase;
    const float* Bbase = B + (size_t)kBase*N + bx*128;

    for (int k0 = 0; k0 < Kper; k0 += 16) {
#pragma unroll
        for (int i = 0; i < 2; i++) {
            int r = aRow + i*64;
            float4 v = *(const float4*)(Abase + (size_t)r*Kd + k0 + aCol);
            As[aCol+0][r] = v.x; As[aCol+1][r] = v.y;
            As[aCol+2][r] = v.z; As[aCol+3][r] = v.w;
        }
#pragma unroll
        for (int i = 0; i < 2; i++) {
            int r = bRow + i*8;
            *(float4*)&Bs[r][bCol] = *(const float4*)(Bbase + (size_t)(k0+r)*N + bCol);
        }
        __syncthreads();
#pragma unroll
        for (int kk = 0; kk < 16; kk++) {
            float4 av0 = *(const float4*)&As[kk][ty*8];
            float4 av1 = *(const float4*)&As[kk][ty*8+4];
            float4 bv0 = *(const float4*)&Bs[kk][tx*8];
            float4 bv1 = *(const float4*)&Bs[kk][tx*8+4];
            unsigned long long a2[4] = {
                pack2f(av0.x, av0.y), pack2f(av0.z, av0.w),
                pack2f(av1.x, av1.y), pack2f(av1.z, av1.w)};
            float bf[8] = {bv0.x,bv0.y,bv0.z,bv0.w,bv1.x,bv1.y,bv1.z,bv1.w};
#pragma unroll
            for (int j = 0; j < 8; j++) {
                unsigned long long bd = pack2f(bf[j], bf[j]);
#pragma unroll
                for (int i = 0; i < 4; i++) ffma2(acc[i][j], a2[i], bd);
            }
        }
        __syncthreads();
    }

    float out[8][8];
#pragma unroll
    for (int i2 = 0; i2 < 4; i2++)
#pragma unroll
        for (int j = 0; j < 8; j++)
            unpack2f(acc[i2][j], out[2*i2][j], out[2*i2+1][j]);

    float bl[8];
#pragma unroll
    for (int j = 0; j < 8; j++) bl[j] = 0.f;
    if (bias != nullptr && !partial) {
#pragma unroll
        for (int j = 0; j < 8; j++) bl[j] = bias[bx*128 + tx*8 + j];
    }

#pragma unroll
    for (int i = 0; i < 8; i++) {
        int row = by*128 + ty*8 + i;
        float* Crow = C + (size_t)row*N + bx*128 + tx*8;
        float vals[8];
#pragma unroll
        for (int j = 0; j < 8; j++) {
            float v = out[i][j];
            if (!partial) {
                v = v * alpha + bl[j];
                if (doRelu) v = fmaxf(v, 0.f);
            }
            vals[j] = v;
        }
        *(float4*)(Crow + 0) = make_float4(vals[0], vals[1], vals[2], vals[3]);
        *(float4*)(Crow + 4) = make_float4(vals[4], vals[5], vals[6], vals[7]);
    }
}

// ---------------- per-row argmax + keep-mask (parallel part of the scan) ----------------
__global__ void argmax_keep_k()
{
    int row = blockIdx.x * 8 + threadIdx.y;
    int lane = threadIdx.x;
    const float* lg = d_logits + (size_t)row * KK;
    float v[8];
    float best = -3.4e38f; int bi = 0;
#pragma unroll
    for (int t = 0; t < 8; t++) {
        int id = lane + t*32;
        v[t] = lg[id];
        if (v[t] > best) { best = v[t]; bi = id; }  // ascending id: strict > keeps smallest
    }
#pragma unroll
    for (int off = 16; off > 0; off >>= 1) {
        float ov = __shfl_down_sync(0xffffffffu, best, off);
        int   oi = __shfl_down_sync(0xffffffffu, bi,   off);
        if (ov > best || (ov == best && oi < bi)) { best = ov; bi = oi; }
    }
    best = __shfl_sync(0xffffffffu, best, 0);
    bi   = __shfl_sync(0xffffffffu, bi,   0);
    if (lane == 0) { d_a0[row] = bi; d_m0[row] = best; }
#pragma unroll
    for (int t = 0; t < 8; t++) {
        int id = lane + t*32;
        float adj = v[t] + 0.1f;
        bool k = (adj > best) || (adj == best && id < bi) || (id == bi);
        unsigned bw = __ballot_sync(0xffffffffu, k);
        if (lane == t) d_keep[(size_t)row*8 + t] = bw;
    }
}

// ---------------- sequential scan, O(1)/step from smem ----------------
extern __shared__ unsigned s_scan[];
__global__ void mode_scan_k(const float* __restrict__ prev_mode)
{
    int b = blockIdx.x;
    unsigned* masks = s_scan;                 // Ss*8 words
    int* a0s = (int*)(s_scan + Ss*8);         // Ss ints
    __shared__ int s_init;
    int tid = threadIdx.x;
    for (int i = tid; i < Ss*8; i += blockDim.x)
        masks[i] = d_keep[(size_t)b*Ss*8 + i];
    for (int i = tid; i < Ss; i += blockDim.x)
        a0s[i] = d_a0[b*Ss + i];
    if (tid < KK && prev_mode[b*KK + tid] > 0.5f) s_init = tid;
    __syncthreads();
    if (tid == 0) {
        int prev = s_init;
        int* outp = d_mode + b*Ss;
        for (int s = 0; s < Ss; s++) {
            unsigned w = masks[s*8 + (prev >> 5)];
            int m = ((w >> (prev & 31)) & 1u) ? prev : a0s[s];
            outp[s] = m;
            prev = m;
        }
    }
}

// ---------------- l2-normalize rows (optionally transposed output) ----------------
__global__ void l2norm_k(const float* __restrict__ in, float* __restrict__ out,
                         int nrows, int transpose)
{
    int row = blockIdx.x * 8 + threadIdx.y;
    if (row >= nrows) return;
    int lane = threadIdx.x;
    const float* p = in + (size_t)row * DM;
    float v[16]; float ss = 0.f;
#pragma unroll
    for (int t = 0; t < 16; t++) { v[t] = p[lane + t*32]; ss += v[t]*v[t]; }
#pragma unroll
    for (int off = 16; off > 0; off >>= 1) ss += __shfl_xor_sync(0xffffffffu, ss, off);
    float rn = 1.f / fmaxf(sqrtf(ss), 1e-12f);
    if (transpose) {
#pragma unroll
        for (int t = 0; t < 16; t++)
            out[(size_t)(lane + t*32) * BANKN + row] = v[t] * rn;
    } else {
#pragma unroll
        for (int t = 0; t < 16; t++)
            out[(size_t)row * DM + lane + t*32] = v[t] * rn;
    }
}

// ---------------- masked softmax over bank slots (in place on d_scores) ----------------
__global__ void softmax_k(const float* __restrict__ used)
{
    int row = blockIdx.x;
    float* s = d_scores + (size_t)row * BANKN;
    int tid = threadIdx.x;  // 256
    __shared__ float red[256];
    float v[16];
    float mx = -3.4e38f;
#pragma unroll
    for (int t = 0; t < 16; t++) {
        int c = tid + t*256;
        float x = s[c];
        x = (used[c] > 0.5f) ? x : -1e30f;
        v[t] = x; mx = fmaxf(mx, x);
    }
    red[tid] = mx; __syncthreads();
    for (int o = 128; o > 0; o >>= 1) { if (tid < o) red[tid] = fmaxf(red[tid], red[tid+o]); __syncthreads(); }
    mx = red[0]; __syncthreads();
    float sum = 0.f;
#pragma unroll
    for (int t = 0; t < 16; t++) { v[t] = expf(v[t] - mx); sum += v[t]; }
    red[tid] = sum; __syncthreads();
    for (int o = 128; o > 0; o >>= 1) { if (tid < o) red[tid] += red[tid+o]; __syncthreads(); }
    float inv = 1.f / red[0];
#pragma unroll
    for (int t = 0; t < 16; t++) s[tid + t*256] = v[t] * inv;
}

// ---------------- reduce split-K partials for the bank table ----------------
__global__ void reduce_bank_k()
{
    int i = blockIdx.x * 256 + threadIdx.x;
    float s = 0.f;
#pragma unroll
    for (int z = 0; z < 8; z++) s += d_part[(size_t)z*KK*DM + i];
    d_bankt[i] = s;
}

// ---------------- r = M[k]+bank[k]; rms-norm with g ----------------
__global__ void rms_k(const float* __restrict__ Mw, const float* __restrict__ g)
{
    int k = blockIdx.x;
    int tid = threadIdx.x;  // 128
    __shared__ float red[128];
    float r[4]; float ss = 0.f;
#pragma unroll
    for (int t = 0; t < 4; t++) {
        int c = tid + t*128;
        r[t] = Mw[(size_t)k*DM + c] + d_bankt[(size_t)k*DM + c];
        ss += r[t]*r[t];
    }
    red[tid] = ss; __syncthreads();
    for (int o = 64; o > 0; o >>= 1) { if (tid < o) red[tid] += red[tid+o]; __syncthreads(); }
    float mean = red[0] / (float)DM;
    float sc = 1.f / sqrtf(mean + 1e-6f);
#pragma unroll
    for (int t = 0; t < 4; t++) {
        int c = tid + t*128;
        d_rn[(size_t)k*DM + c] = r[t] * g[c] * sc;
    }
}

// ---------------- gather y rows + scatter one-hot modes ----------------
__global__ void assemble_k(float* __restrict__ y, float* __restrict__ modes, int writeModes)
{
    int row = blockIdx.x;
    int t = threadIdx.x;  // 256
    int m = d_mode[row];
    float4 v = ((const float4*)(d_ytab + (size_t)m * DOUT))[t];
    ((float4*)(y + (size_t)row * DOUT))[t] = v;
    if (writeModes)
        modes[(size_t)row * KK + t] = (t == m) ? 1.f : 0.f;
}

// ---------------- launch ----------------
extern "C" void kernel_launch(void* const* d_in, const int* in_sizes, int n_in,
                              void* d_out, int out_size)
{
    const float* x     = (const float*)d_in[0];
    const float* prevm = (const float*)d_in[1];
    const float* Wtr_w = (const float*)d_in[2];
    const float* Wtr_b = (const float*)d_in[3];
    const float* Wms_w = (const float*)d_in[4];
    const float* Wms_b = (const float*)d_in[5];
    const float* Mw    = (const float*)d_in[6];
    const float* g     = (const float*)d_in[7];
    const float* Wrd_w = (const float*)d_in[8];
    const float* Wrd_b = (const float*)d_in[9];
    const float* bkeys = (const float*)d_in[10];
    const float* bvals = (const float*)d_in[11];
    const float* bused = (const float*)d_in[12];

    float* y = (float*)d_out;
    int writeModes = (out_size >= (int)((size_t)RR*DOUT + (size_t)RR*KK)) ? 1 : 0;
    float* modes = y + (size_t)RR * DOUT;

    void *ph, *plog, *pknT, *pqn, *pscores, *ppart, *prn, *pytab;
    cudaGetSymbolAddress(&ph, d_h);
    cudaGetSymbolAddress(&plog, d_logits);
    cudaGetSymbolAddress(&pknT, d_knT);
    cudaGetSymbolAddress(&pqn, d_qn);
    cudaGetSymbolAddress(&pscores, d_scores);
    cudaGetSymbolAddress(&ppart, d_part);
    cudaGetSymbolAddress(&prn, d_rn);
    cudaGetSymbolAddress(&pytab, d_ytab);

    cudaFuncSetAttribute(mode_scan_k, cudaFuncAttributeMaxDynamicSharedMemorySize, 73728);

    // GEMM1: h = relu(x @ Wtr + b)   [16384,2048]
    gemm128<<<dim3(HH/128, RR/128), 256>>>(x, Wtr_w, Wtr_b, (float*)ph, RR, HH, DIN, 1.f, 1);
    // GEMM2: logits = h @ Wms + b    [16384,256]
    gemm128<<<dim3(KK/128, RR/128), 256>>>((const float*)ph, Wms_w, Wms_b, (float*)plog, RR, KK, HH, 1.f, 0);
    // per-row argmax + keep masks
    argmax_keep_k<<<RR/8, dim3(32,8)>>>();
    // sequential mode scan (8 independent batch chains)
    mode_scan_k<<<Bb, 256, 73728>>>(prevm);

    // --- mode table construction (independent of scan, tiny) ---
    l2norm_k<<<BANKN/8, dim3(32,8)>>>(bkeys, (float*)pknT, BANKN, 1);
    l2norm_k<<<KK/8,    dim3(32,8)>>>(Mw,    (float*)pqn,  KK,    0);
    // scores = 4 * qn @ knT          [256,4096]
    gemm128<<<dim3(BANKN/128, KK/128), 256>>>((const float*)pqn, (const float*)pknT, nullptr,
                                              (float*)pscores, KK, BANKN, DM, 4.0f, 0);
    softmax_k<<<KK, 256>>>(bused);
    // bank = attn @ bank_vals        [256,512]  (split-K 8)
    gemm128<<<dim3(DM/128, KK/128, 8), 256>>>((const float*)pscores, bvals, nullptr,
                                              (float*)ppart, KK, DM, BANKN, 1.f, 0);
    reduce_bank_k<<<(KK*DM)/256, 256>>>();
    rms_k<<<KK, 128>>>(Mw, g);
    // y_tab = rn @ Wrd + b           [256,1024]
    gemm128<<<dim3(DOUT/128, KK/128), 256>>>((const float*)prn, Wrd_w, Wrd_b,
                                             (float*)pytab, KK, DOUT, DM, 1.f, 0);

    // gather + one-hot scatter
    assemble_k<<<RR, 256>>>(y, modes, writeModes);
}

// round 3
// speedup vs baseline: 1.0008x; 1.0008x over previous
#include <cuda_runtime.h>
#include <math.h>

// ---------------- problem dims ----------------
#define Bb   8
#define Ss   2048
#define RR   (Bb*Ss)       // 16384 rows
#define DIN  1024
#define HH   2048
#define KK   256
#define DM   512
#define DOUT 1024
#define BANKN 4096

// ---------------- device scratch (static, allowed) ----------------
__device__ float    d_h[(size_t)RR*HH];        // 134 MB
__device__ float    d_logits[(size_t)RR*KK];   // 16.8 MB
__device__ int      d_a0[RR];
__device__ float    d_m0[RR];
__device__ unsigned d_keep[(size_t)RR*8];      // 256-bit keep masks
__device__ int      d_mode[RR];
__device__ float    d_knT[(size_t)DM*BANKN];   // normalized bank keys, transposed [DM,BANK]
__device__ float    d_qn[KK*DM];               // normalized M rows
__device__ float    d_scores[(size_t)KK*BANKN];// scores / attn (in place)
__device__ float    d_part[8*KK*DM];           // split-K partials
__device__ float    d_bankt[KK*DM];            // bank table
__device__ float    d_rn[KK*DM];               // rms-normed table
__device__ float    d_ytab[KK*DOUT];           // final per-mode output rows

// ---------------- packed f32x2 helpers ----------------
__device__ __forceinline__ unsigned long long pack2f(float lo, float hi){
    unsigned long long r; asm("mov.b64 %0, {%1,%2};" : "=l"(r) : "f"(lo), "f"(hi)); return r;
}
__device__ __forceinline__ void unpack2f(unsigned long long v, float& lo, float& hi){
    asm("mov.b64 {%0,%1}, %2;" : "=f"(lo), "=f"(hi) : "l"(v));
}
__device__ __forceinline__ void ffma2(unsigned long long& d, unsigned long long a, unsigned long long b){
    asm("fma.rn.f32x2 %0, %1, %2, %0;" : "+l"(d) : "l"(a), "l"(b));
}

// ---------------- 128x128x16 fp32 GEMM (dual-issue f32x2 inner loop) ----------------
// C[M,N] = alpha*(A[M,K] @ B[K,N]) + bias[N], optional relu.
// gridDim.z>1 => split-K: writes raw partials to C + z*M*N (no alpha/bias/relu).
__global__ void __launch_bounds__(256, 2) gemm128(
    const float* __restrict__ A, const float* __restrict__ B,
    const float* __restrict__ bias, float* __restrict__ C,
    int M, int N, int Kd, float alpha, int doRelu)
{
    __shared__ float As[16][128];
    __shared__ float Bs[16][128];
    const int tid = threadIdx.x;
    const int bx = blockIdx.x, by = blockIdx.y;
    const int nz = gridDim.z;
    const int Kper = Kd / nz;
    const int kBase = blockIdx.z * Kper;
    const bool partial = (nz > 1);
    if (partial) C += (size_t)blockIdx.z * (size_t)M * N;

    const int aRow = tid >> 2;            // 0..63
    const int aCol = (tid & 3) << 2;      // 0,4,8,12
    const int bRow = tid >> 5;            // 0..7
    const int bCol = (tid & 31) << 2;     // 0..124
    const int tx = tid & 15, ty = tid >> 4;

    unsigned long long acc[4][8];
#pragma unroll
    for (int i = 0; i < 4; i++)
#pragma unroll
        for (int j = 0; j < 8; j++) acc[i][j] = 0ull;

    const float* Abase = A + (size_t)(by*128)*Kd + kBase;
    const float* Bbase = B + (size_t)kBase*N + bx*128;

    for (int k0 = 0; k0 < Kper; k0 += 16) {
#pragma unroll
        for (int i = 0; i < 2; i++) {
            int r = aRow + i*64;
            float4 v = *(const float4*)(Abase + (size_t)r*Kd + k0 + aCol);
            As[aCol+0][r] = v.x; As[aCol+1][r] = v.y;
            As[aCol+2][r] = v.z; As[aCol+3][r] = v.w;
        }
#pragma unroll
        for (int i = 0; i < 2; i++) {
            int r = bRow + i*8;
            *(float4*)&Bs[r][bCol] = *(const float4*)(Bbase + (size_t)(k0+r)*N + bCol);
        }
        __syncthreads();
#pragma unroll
        for (int kk = 0; kk < 16; kk++) {
            float4 av0 = *(const float4*)&As[kk][ty*8];
            float4 av1 = *(const float4*)&As[kk][ty*8+4];
            float4 bv0 = *(const float4*)&Bs[kk][tx*8];
            float4 bv1 = *(const float4*)&Bs[kk][tx*8+4];
            unsigned long long a2[4] = {
                pack2f(av0.x, av0.y), pack2f(av0.z, av0.w),
                pack2f(av1.x, av1.y), pack2f(av1.z, av1.w)};
            float bf[8] = {bv0.x,bv0.y,bv0.z,bv0.w,bv1.x,bv1.y,bv1.z,bv1.w};
#pragma unroll
            for (int j = 0; j < 8; j++) {
                unsigned long long bd = pack2f(bf[j], bf[j]);
#pragma unroll
                for (int i = 0; i < 4; i++) ffma2(acc[i][j], a2[i], bd);
            }
        }
        __syncthreads();
    }

    float out[8][8];
#pragma unroll
    for (int i2 = 0; i2 < 4; i2++)
#pragma unroll
        for (int j = 0; j < 8; j++)
            unpack2f(acc[i2][j], out[2*i2][j], out[2*i2+1][j]);

    float bl[8];
#pragma unroll
    for (int j = 0; j < 8; j++) bl[j] = 0.f;
    if (bias != nullptr && !partial) {
#pragma unroll
        for (int j = 0; j < 8; j++) bl[j] = bias[bx*128 + tx*8 + j];
    }

#pragma unroll
    for (int i = 0; i < 8; i++) {
        int row = by*128 + ty*8 + i;
        float* Crow = C + (size_t)row*N + bx*128 + tx*8;
        float vals[8];
#pragma unroll
        for (int j = 0; j < 8; j++) {
            float v = out[i][j];
            if (!partial) {
                v = v * alpha + bl[j];
                if (doRelu) v = fmaxf(v, 0.f);
            }
            vals[j] = v;
        }
        *(float4*)(Crow + 0) = make_float4(vals[0], vals[1], vals[2], vals[3]);
        *(float4*)(Crow + 4) = make_float4(vals[4], vals[5], vals[6], vals[7]);
    }
}

// ---------------- per-row argmax + keep-mask (parallel part of the scan) ----------------
__global__ void argmax_keep_k()
{
    int row = blockIdx.x * 8 + threadIdx.y;
    int lane = threadIdx.x;
    const float* lg = d_logits + (size_t)row * KK;
    float v[8];
    float best = -3.4e38f; int bi = 0;
#pragma unroll
    for (int t = 0; t < 8; t++) {
        int id = lane + t*32;
        v[t] = lg[id];
        if (v[t] > best) { best = v[t]; bi = id; }  // ascending id: strict > keeps smallest
    }
#pragma unroll
    for (int off = 16; off > 0; off >>= 1) {
        float ov = __shfl_down_sync(0xffffffffu, best, off);
        int   oi = __shfl_down_sync(0xffffffffu, bi,   off);
        if (ov > best || (ov == best && oi < bi)) { best = ov; bi = oi; }
    }
    best = __shfl_sync(0xffffffffu, best, 0);
    bi   = __shfl_sync(0xffffffffu, bi,   0);
    if (lane == 0) { d_a0[row] = bi; d_m0[row] = best; }
#pragma unroll
    for (int t = 0; t < 8; t++) {
        int id = lane + t*32;
        float adj = v[t] + 0.1f;
        bool k = (adj > best) || (adj == best && id < bi) || (id == bi);
        unsigned bw = __ballot_sync(0xffffffffu, k);
        if (lane == t) d_keep[(size_t)row*8 + t] = bw;
    }
}

// ---------------- sequential scan, O(1)/step from smem ----------------
extern __shared__ unsigned s_scan[];
__global__ void mode_scan_k(const float* __restrict__ prev_mode)
{
    int b = blockIdx.x;
    unsigned* masks = s_scan;                 // Ss*8 words
    int* a0s = (int*)(s_scan + Ss*8);         // Ss ints
    __shared__ int s_init;
    int tid = threadIdx.x;
    for (int i = tid; i < Ss*8; i += blockDim.x)
        masks[i] = d_keep[(size_t)b*Ss*8 + i];
    for (int i = tid; i < Ss; i += blockDim.x)
        a0s[i] = d_a0[b*Ss + i];
    if (tid < KK && prev_mode[b*KK + tid] > 0.5f) s_init = tid;
    __syncthreads();
    if (tid == 0) {
        int prev = s_init;
        int* outp = d_mode + b*Ss;
        for (int s = 0; s < Ss; s++) {
            unsigned w = masks[s*8 + (prev >> 5)];
            int m = ((w >> (prev & 31)) & 1u) ? prev : a0s[s];
            outp[s] = m;
            prev = m;
        }
    }
}

// ---------------- l2-normalize rows (optionally transposed output) ----------------
__global__ void l2norm_k(const float* __restrict__ in, float* __restrict__ out,
                         int nrows, int transpose)
{
    int row = blockIdx.x * 8 + threadIdx.y;
    if (row >= nrows) return;
    int lane = threadIdx.x;
    const float* p = in + (size_t)row * DM;
    float v[16]; float ss = 0.f;
#pragma unroll
    for (int t = 0; t < 16; t++) { v[t] = p[lane + t*32]; ss += v[t]*v[t]; }
#pragma unroll
    for (int off = 16; off > 0; off >>= 1) ss += __shfl_xor_sync(0xffffffffu, ss, off);
    float rn = 1.f / fmaxf(sqrtf(ss), 1e-12f);
    if (transpose) {
#pragma unroll
        for (int t = 0; t < 16; t++)
            out[(size_t)(lane + t*32) * BANKN + row] = v[t] * rn;
    } else {
#pragma unroll
        for (int t = 0; t < 16; t++)
            out[(size_t)row * DM + lane + t*32] = v[t] * rn;
    }
}

// ---------------- masked softmax over bank slots (in place on d_scores) ----------------
__global__ void softmax_k(const float* __restrict__ used)
{
    int row = blockIdx.x;
    float* s = d_scores + (size_t)row * BANKN;
    int tid = threadIdx.x;  // 256
    __shared__ float red[256];
    float v[16];
    float mx = -3.4e38f;
#pragma unroll
    for (int t = 0; t < 16; t++) {
        int c = tid + t*256;
        float x = s[c];
        x = (used[c] > 0.5f) ? x : -1e30f;
        v[t] = x; mx = fmaxf(mx, x);
    }
    red[tid] = mx; __syncthreads();
    for (int o = 128; o > 0; o >>= 1) { if (tid < o) red[tid] = fmaxf(red[tid], red[tid+o]); __syncthreads(); }
    mx = red[0]; __syncthreads();
    float sum = 0.f;
#pragma unroll
    for (int t = 0; t < 16; t++) { v[t] = expf(v[t] - mx); sum += v[t]; }
    red[tid] = sum; __syncthreads();
    for (int o = 128; o > 0; o >>= 1) { if (tid < o) red[tid] += red[tid+o]; __syncthreads(); }
    float inv = 1.f / red[0];
#pragma unroll
    for (int t = 0; t < 16; t++) s[tid + t*256] = v[t] * inv;
}

// ---------------- reduce split-K partials for the bank table ----------------
__global__ void reduce_bank_k()
{
    int i = blockIdx.x * 256 + threadIdx.x;
    float s = 0.f;
#pragma unroll
    for (int z = 0; z < 8; z++) s += d_part[(size_t)z*KK*DM + i];
    d_bankt[i] = s;
}

// ---------------- r = M[k]+bank[k]; rms-norm with g ----------------
__global__ void rms_k(const float* __restrict__ Mw, const float* __restrict__ g)
{
    int k = blockIdx.x;
    int tid = threadIdx.x;  // 128
    __shared__ float red[128];
    float r[4]; float ss = 0.f;
#pragma unroll
    for (int t = 0; t < 4; t++) {
        int c = tid + t*128;
        r[t] = Mw[(size_t)k*DM + c] + d_bankt[(size_t)k*DM + c];
        ss += r[t]*r[t];
    }
    red[tid] = ss; __syncthreads();
    for (int o = 64; o > 0; o >>= 1) { if (tid < o) red[tid] += red[tid+o]; __syncthreads(); }
    float mean = red[0] / (float)DM;
    float sc = 1.f / sqrtf(mean + 1e-6f);
#pragma unroll
    for (int t = 0; t < 4; t++) {
        int c = tid + t*128;
        d_rn[(size_t)k*DM + c] = r[t] * g[c] * sc;
    }
}

// ---------------- gather y rows + scatter one-hot modes ----------------
__global__ void assemble_k(float* __restrict__ y, float* __restrict__ modes, int writeModes)
{
    int row = blockIdx.x;
    int t = threadIdx.x;  // 256
    int m = d_mode[row];
    float4 v = ((const float4*)(d_ytab + (size_t)m * DOUT))[t];
    ((float4*)(y + (size_t)row * DOUT))[t] = v;
    if (writeModes)
        modes[(size_t)row * KK + t] = (t == m) ? 1.f : 0.f;
}

// ---------------- launch ----------------
extern "C" void kernel_launch(void* const* d_in, const int* in_sizes, int n_in,
                              void* d_out, int out_size)
{
    const float* x     = (const float*)d_in[0];
    const float* prevm = (const float*)d_in[1];
    const float* Wtr_w = (const float*)d_in[2];
    const float* Wtr_b = (const float*)d_in[3];
    const float* Wms_w = (const float*)d_in[4];
    const float* Wms_b = (const float*)d_in[5];
    const float* Mw    = (const float*)d_in[6];
    const float* g     = (const float*)d_in[7];
    const float* Wrd_w = (const float*)d_in[8];
    const float* Wrd_b = (const float*)d_in[9];
    const float* bkeys = (const float*)d_in[10];
    const float* bvals = (const float*)d_in[11];
    const float* bused = (const float*)d_in[12];

    float* y = (float*)d_out;
    int writeModes = (out_size >= (int)((size_t)RR*DOUT + (size_t)RR*KK)) ? 1 : 0;
    float* modes = y + (size_t)RR * DOUT;

    void *ph, *plog, *pknT, *pqn, *pscores, *ppart, *prn, *pytab;
    cudaGetSymbolAddress(&ph, d_h);
    cudaGetSymbolAddress(&plog, d_logits);
    cudaGetSymbolAddress(&pknT, d_knT);
    cudaGetSymbolAddress(&pqn, d_qn);
    cudaGetSymbolAddress(&pscores, d_scores);
    cudaGetSymbolAddress(&ppart, d_part);
    cudaGetSymbolAddress(&prn, d_rn);
    cudaGetSymbolAddress(&pytab, d_ytab);

    cudaFuncSetAttribute(mode_scan_k, cudaFuncAttributeMaxDynamicSharedMemorySize, 73728);

    // GEMM1: h = relu(x @ Wtr + b)   [16384,2048]
    gemm128<<<dim3(HH/128, RR/128), 256>>>(x, Wtr_w, Wtr_b, (float*)ph, RR, HH, DIN, 1.f, 1);
    // GEMM2: logits = h @ Wms + b    [16384,256]
    gemm128<<<dim3(KK/128, RR/128), 256>>>((const float*)ph, Wms_w, Wms_b, (float*)plog, RR, KK, HH, 1.f, 0);
    // per-row argmax + keep masks
    argmax_keep_k<<<RR/8, dim3(32,8)>>>();
    // sequential mode scan (8 independent batch chains)
    mode_scan_k<<<Bb, 256, 73728>>>(prevm);

    // --- mode table construction (independent of scan, tiny) ---
    l2norm_k<<<BANKN/8, dim3(32,8)>>>(bkeys, (float*)pknT, BANKN, 1);
    l2norm_k<<<KK/8,    dim3(32,8)>>>(Mw,    (float*)pqn,  KK,    0);
    // scores = 4 * qn @ knT          [256,4096]
    gemm128<<<dim3(BANKN/128, KK/128), 256>>>((const float*)pqn, (const float*)pknT, nullptr,
                                              (float*)pscores, KK, BANKN, DM, 4.0f, 0);
    softmax_k<<<KK, 256>>>(bused);
    // bank = attn @ bank_vals        [256,512]  (split-K 8)
    gemm128<<<dim3(DM/128, KK/128, 8), 256>>>((const float*)pscores, bvals, nullptr,
                                              (float*)ppart, KK, DM, BANKN, 1.f, 0);
    reduce_bank_k<<<(KK*DM)/256, 256>>>();
    rms_k<<<KK, 128>>>(Mw, g);
    // y_tab = rn @ Wrd + b           [256,1024]
    gemm128<<<dim3(DOUT/128, KK/128), 256>>>((const float*)prn, Wrd_w, Wrd_b,
                                             (float*)pytab, KK, DOUT, DM, 1.f, 0);

    // gather + one-hot scatter
    assemble_k<<<RR, 256>>>(y, modes, writeModes);
}

// round 4
// speedup vs baseline: 1.0013x; 1.0006x over previous
#include <cuda_runtime.h>
#include <math.h>

// ---------------- problem dims ----------------
#define Bb   8
#define Ss   2048
#define RR   (Bb*Ss)       // 16384 rows
#define DIN  1024
#define HH   2048
#define KK   256
#define DM   512
#define DOUT 1024
#define BANKN 4096

// ---------------- device scratch (static, allowed) ----------------
__device__ float    d_h[(size_t)RR*HH];        // 134 MB
__device__ float    d_logits[(size_t)RR*KK];   // 16.8 MB
__device__ int      d_a0[RR];
__device__ float    d_m0[RR];
__device__ unsigned d_keep[(size_t)RR*8];      // 256-bit keep masks
__device__ int      d_mode[RR];
__device__ float    d_knT[(size_t)DM*BANKN];   // normalized bank keys, transposed [DM,BANK]
__device__ float    d_qn[KK*DM];               // normalized M rows
__device__ float    d_scores[(size_t)KK*BANKN];// scores / attn (in place)
__device__ float    d_part[8*KK*DM];           // split-K partials
__device__ float    d_bankt[KK*DM];            // bank table
__device__ float    d_rn[KK*DM];               // rms-normed table
__device__ float    d_ytab[KK*DOUT];           // final per-mode output rows

// ---------------- packed f32x2 helpers ----------------
__device__ __forceinline__ unsigned long long pack2f(float lo, float hi){
    unsigned long long r; asm("mov.b64 %0, {%1,%2};" : "=l"(r) : "f"(lo), "f"(hi)); return r;
}
__device__ __forceinline__ void unpack2f(unsigned long long v, float& lo, float& hi){
    asm("mov.b64 {%0,%1}, %2;" : "=f"(lo), "=f"(hi) : "l"(v));
}
__device__ __forceinline__ void ffma2(unsigned long long& d, unsigned long long a, unsigned long long b){
    asm("fma.rn.f32x2 %0, %1, %2, %0;" : "+l"(d) : "l"(a), "l"(b));
}

// ---------------- 128x128x16 fp32 GEMM (dual-issue f32x2 inner loop) ----------------
// C[M,N] = alpha*(A[M,K] @ B[K,N]) + bias[N], optional relu.
// gridDim.z>1 => split-K: writes raw partials to C + z*M*N (no alpha/bias/relu).
__global__ void __launch_bounds__(256, 2) gemm128(
    const float* __restrict__ A, const float* __restrict__ B,
    const float* __restrict__ bias, float* __restrict__ C,
    int M, int N, int Kd, float alpha, int doRelu)
{
    __shared__ float As[16][128];
    __shared__ float Bs[16][128];
    const int tid = threadIdx.x;
    const int bx = blockIdx.x, by = blockIdx.y;
    const int nz = gridDim.z;
    const int Kper = Kd / nz;
    const int kBase = blockIdx.z * Kper;
    const bool partial = (nz > 1);
    if (partial) C += (size_t)blockIdx.z * (size_t)M * N;

    const int aRow = tid >> 2;            // 0..63
    const int aCol = (tid & 3) << 2;      // 0,4,8,12
    const int bRow = tid >> 5;            // 0..7
    const int bCol = (tid & 31) << 2;     // 0..124
    const int tx = tid & 15, ty = tid >> 4;

    unsigned long long acc[4][8];
#pragma unroll
    for (int i = 0; i < 4; i++)
#pragma unroll
        for (int j = 0; j < 8; j++) acc[i][j] = 0ull;

    const float* Abase = A + (size_t)(by*128)*Kd + kBase;
    const float* Bbase = B + (size_t)kBase*N + bx*128;

    for (int k0 = 0; k0 < Kper; k0 += 16) {
#pragma unroll
        for (int i = 0; i < 2; i++) {
            int r = aRow + i*64;
            float4 v = *(const float4*)(Abase + (size_t)r*Kd + k0 + aCol);
            As[aCol+0][r] = v.x; As[aCol+1][r] = v.y;
            As[aCol+2][r] = v.z; As[aCol+3][r] = v.w;
        }
#pragma unroll
        for (int i = 0; i < 2; i++) {
            int r = bRow + i*8;
            *(float4*)&Bs[r][bCol] = *(const float4*)(Bbase + (size_t)(k0+r)*N + bCol);
        }
        __syncthreads();
#pragma unroll
        for (int kk = 0; kk < 16; kk++) {
            float4 av0 = *(const float4*)&As[kk][ty*8];
            float4 av1 = *(const float4*)&As[kk][ty*8+4];
            float4 bv0 = *(const float4*)&Bs[kk][tx*8];
            float4 bv1 = *(const float4*)&Bs[kk][tx*8+4];
            unsigned long long a2[4] = {
                pack2f(av0.x, av0.y), pack2f(av0.z, av0.w),
                pack2f(av1.x, av1.y), pack2f(av1.z, av1.w)};
            float bf[8] = {bv0.x,bv0.y,bv0.z,bv0.w,bv1.x,bv1.y,bv1.z,bv1.w};
#pragma unroll
            for (int j = 0; j < 8; j++) {
                unsigned long long bd = pack2f(bf[j], bf[j]);
#pragma unroll
                for (int i = 0; i < 4; i++) ffma2(acc[i][j], a2[i], bd);
            }
        }
        __syncthreads();
    }

    float out[8][8];
#pragma unroll
    for (int i2 = 0; i2 < 4; i2++)
#pragma unroll
        for (int j = 0; j < 8; j++)
            unpack2f(acc[i2][j], out[2*i2][j], out[2*i2+1][j]);

    float bl[8];
#pragma unroll
    for (int j = 0; j < 8; j++) bl[j] = 0.f;
    if (bias != nullptr && !partial) {
#pragma unroll
        for (int j = 0; j < 8; j++) bl[j] = bias[bx*128 + tx*8 + j];
    }

#pragma unroll
    for (int i = 0; i < 8; i++) {
        int row = by*128 + ty*8 + i;
        float* Crow = C + (size_t)row*N + bx*128 + tx*8;
        float vals[8];
#pragma unroll
        for (int j = 0; j < 8; j++) {
            float v = out[i][j];
            if (!partial) {
                v = v * alpha + bl[j];
                if (doRelu) v = fmaxf(v, 0.f);
            }
            vals[j] = v;
        }
        *(float4*)(Crow + 0) = make_float4(vals[0], vals[1], vals[2], vals[3]);
        *(float4*)(Crow + 4) = make_float4(vals[4], vals[5], vals[6], vals[7]);
    }
}

// ---------------- per-row argmax + keep-mask (parallel part of the scan) ----------------
__global__ void argmax_keep_k()
{
    int row = blockIdx.x * 8 + threadIdx.y;
    int lane = threadIdx.x;
    const float* lg = d_logits + (size_t)row * KK;
    float v[8];
    float best = -3.4e38f; int bi = 0;
#pragma unroll
    for (int t = 0; t < 8; t++) {
        int id = lane + t*32;
        v[t] = lg[id];
        if (v[t] > best) { best = v[t]; bi = id; }  // ascending id: strict > keeps smallest
    }
#pragma unroll
    for (int off = 16; off > 0; off >>= 1) {
        float ov = __shfl_down_sync(0xffffffffu, best, off);
        int   oi = __shfl_down_sync(0xffffffffu, bi,   off);
        if (ov > best || (ov == best && oi < bi)) { best = ov; bi = oi; }
    }
    best = __shfl_sync(0xffffffffu, best, 0);
    bi   = __shfl_sync(0xffffffffu, bi,   0);
    if (lane == 0) { d_a0[row] = bi; d_m0[row] = best; }
#pragma unroll
    for (int t = 0; t < 8; t++) {
        int id = lane + t*32;
        float adj = v[t] + 0.1f;
        bool k = (adj > best) || (adj == best && id < bi) || (id == bi);
        unsigned bw = __ballot_sync(0xffffffffu, k);
        if (lane == t) d_keep[(size_t)row*8 + t] = bw;
    }
}

// ---------------- sequential scan, O(1)/step from smem ----------------
extern __shared__ unsigned s_scan[];
__global__ void mode_scan_k(const float* __restrict__ prev_mode)
{
    int b = blockIdx.x;
    unsigned* masks = s_scan;                 // Ss*8 words
    int* a0s = (int*)(s_scan + Ss*8);         // Ss ints
    __shared__ int s_init;
    int tid = threadIdx.x;
    for (int i = tid; i < Ss*8; i += blockDim.x)
        masks[i] = d_keep[(size_t)b*Ss*8 + i];
    for (int i = tid; i < Ss; i += blockDim.x)
        a0s[i] = d_a0[b*Ss + i];
    if (tid < KK && prev_mode[b*KK + tid] > 0.5f) s_init = tid;
    __syncthreads();
    if (tid == 0) {
        int prev = s_init;
        int* outp = d_mode + b*Ss;
        for (int s = 0; s < Ss; s++) {
            unsigned w = masks[s*8 + (prev >> 5)];
            int m = ((w >> (prev & 31)) & 1u) ? prev : a0s[s];
            outp[s] = m;
            prev = m;
        }
    }
}

// ---------------- l2-normalize rows (optionally transposed output) ----------------
__global__ void l2norm_k(const float* __restrict__ in, float* __restrict__ out,
                         int nrows, int transpose)
{
    int row = blockIdx.x * 8 + threadIdx.y;
    if (row >= nrows) return;
    int lane = threadIdx.x;
    const float* p = in + (size_t)row * DM;
    float v[16]; float ss = 0.f;
#pragma unroll
    for (int t = 0; t < 16; t++) { v[t] = p[lane + t*32]; ss += v[t]*v[t]; }
#pragma unroll
    for (int off = 16; off > 0; off >>= 1) ss += __shfl_xor_sync(0xffffffffu, ss, off);
    float rn = 1.f / fmaxf(sqrtf(ss), 1e-12f);
    if (transpose) {
#pragma unroll
        for (int t = 0; t < 16; t++)
            out[(size_t)(lane + t*32) * BANKN + row] = v[t] * rn;
    } else {
#pragma unroll
        for (int t = 0; t < 16; t++)
            out[(size_t)row * DM + lane + t*32] = v[t] * rn;
    }
}

// ---------------- masked softmax over bank slots (in place on d_scores) ----------------
__global__ void softmax_k(const float* __restrict__ used)
{
    int row = blockIdx.x;
    float* s = d_scores + (size_t)row * BANKN;
    int tid = threadIdx.x;  // 256
    __shared__ float red[256];
    float v[16];
    float mx = -3.4e38f;
#pragma unroll
    for (int t = 0; t < 16; t++) {
        int c = tid + t*256;
        float x = s[c];
        x = (used[c] > 0.5f) ? x : -1e30f;
        v[t] = x; mx = fmaxf(mx, x);
    }
    red[tid] = mx; __syncthreads();
    for (int o = 128; o > 0; o >>= 1) { if (tid < o) red[tid] = fmaxf(red[tid], red[tid+o]); __syncthreads(); }
    mx = red[0]; __syncthreads();
    float sum = 0.f;
#pragma unroll
    for (int t = 0; t < 16; t++) { v[t] = expf(v[t] - mx); sum += v[t]; }
    red[tid] = sum; __syncthreads();
    for (int o = 128; o > 0; o >>= 1) { if (tid < o) red[tid] += red[tid+o]; __syncthreads(); }
    float inv = 1.f / red[0];
#pragma unroll
    for (int t = 0; t < 16; t++) s[tid + t*256] = v[t] * inv;
}

// ---------------- reduce split-K partials for the bank table ----------------
__global__ void reduce_bank_k()
{
    int i = blockIdx.x * 256 + threadIdx.x;
    float s = 0.f;
#pragma unroll
    for (int z = 0; z < 8; z++) s += d_part[(size_t)z*KK*DM + i];
    d_bankt[i] = s;
}

// ---------------- r = M[k]+bank[k]; rms-norm with g ----------------
__global__ void rms_k(const float* __restrict__ Mw, const float* __restrict__ g)
{
    int k = blockIdx.x;
    int tid = threadIdx.x;  // 128
    __shared__ float red[128];
    float r[4]; float ss = 0.f;
#pragma unroll
    for (int t = 0; t < 4; t++) {
        int c = tid + t*128;
        r[t] = Mw[(size_t)k*DM + c] + d_bankt[(size_t)k*DM + c];
        ss += r[t]*r[t];
    }
    red[tid] = ss; __syncthreads();
    for (int o = 64; o > 0; o >>= 1) { if (tid < o) red[tid] += red[tid+o]; __syncthreads(); }
    float mean = red[0] / (float)DM;
    float sc = 1.f / sqrtf(mean + 1e-6f);
#pragma unroll
    for (int t = 0; t < 4; t++) {
        int c = tid + t*128;
        d_rn[(size_t)k*DM + c] = r[t] * g[c] * sc;
    }
}

// ---------------- gather y rows + scatter one-hot modes ----------------
__global__ void assemble_k(float* __restrict__ y, float* __restrict__ modes, int writeModes)
{
    int row = blockIdx.x;
    int t = threadIdx.x;  // 256
    int m = d_mode[row];
    float4 v = ((const float4*)(d_ytab + (size_t)m * DOUT))[t];
    ((float4*)(y + (size_t)row * DOUT))[t] = v;
    if (writeModes)
        modes[(size_t)row * KK + t] = (t == m) ? 1.f : 0.f;
}

// ---------------- launch ----------------
extern "C" void kernel_launch(void* const* d_in, const int* in_sizes, int n_in,
                              void* d_out, int out_size)
{
    const float* x     = (const float*)d_in[0];
    const float* prevm = (const float*)d_in[1];
    const float* Wtr_w = (const float*)d_in[2];
    const float* Wtr_b = (const float*)d_in[3];
    const float* Wms_w = (const float*)d_in[4];
    const float* Wms_b = (const float*)d_in[5];
    const float* Mw    = (const float*)d_in[6];
    const float* g     = (const float*)d_in[7];
    const float* Wrd_w = (const float*)d_in[8];
    const float* Wrd_b = (const float*)d_in[9];
    const float* bkeys = (const float*)d_in[10];
    const float* bvals = (const float*)d_in[11];
    const float* bused = (const float*)d_in[12];

    float* y = (float*)d_out;
    int writeModes = (out_size >= (int)((size_t)RR*DOUT + (size_t)RR*KK)) ? 1 : 0;
    float* modes = y + (size_t)RR * DOUT;

    void *ph, *plog, *pknT, *pqn, *pscores, *ppart, *prn, *pytab;
    cudaGetSymbolAddress(&ph, d_h);
    cudaGetSymbolAddress(&plog, d_logits);
    cudaGetSymbolAddress(&pknT, d_knT);
    cudaGetSymbolAddress(&pqn, d_qn);
    cudaGetSymbolAddress(&pscores, d_scores);
    cudaGetSymbolAddress(&ppart, d_part);
    cudaGetSymbolAddress(&prn, d_rn);
    cudaGetSymbolAddress(&pytab, d_ytab);

    cudaFuncSetAttribute(mode_scan_k, cudaFuncAttributeMaxDynamicSharedMemorySize, 73728);

    // GEMM1: h = relu(x @ Wtr + b)   [16384,2048]
    gemm128<<<dim3(HH/128, RR/128), 256>>>(x, Wtr_w, Wtr_b, (float*)ph, RR, HH, DIN, 1.f, 1);
    // GEMM2: logits = h @ Wms + b    [16384,256]
    gemm128<<<dim3(KK/128, RR/128), 256>>>((const float*)ph, Wms_w, Wms_b, (float*)plog, RR, KK, HH, 1.f, 0);
    // per-row argmax + keep masks
    argmax_keep_k<<<RR/8, dim3(32,8)>>>();
    // sequential mode scan (8 independent batch chains)
    mode_scan_k<<<Bb, 256, 73728>>>(prevm);

    // --- mode table construction (independent of scan, tiny) ---
    l2norm_k<<<BANKN/8, dim3(32,8)>>>(bkeys, (float*)pknT, BANKN, 1);
    l2norm_k<<<KK/8,    dim3(32,8)>>>(Mw,    (float*)pqn,  KK,    0);
    // scores = 4 * qn @ knT          [256,4096]
    gemm128<<<dim3(BANKN/128, KK/128), 256>>>((const float*)pqn, (const float*)pknT, nullptr,
                                              (float*)pscores, KK, BANKN, DM, 4.0f, 0);
    softmax_k<<<KK, 256>>>(bused);
    // bank = attn @ bank_vals        [256,512]  (split-K 8)
    gemm128<<<dim3(DM/128, KK/128, 8), 256>>>((const float*)pscores, bvals, nullptr,
                                              (float*)ppart, KK, DM, BANKN, 1.f, 0);
    reduce_bank_k<<<(KK*DM)/256, 256>>>();
    rms_k<<<KK, 128>>>(Mw, g);
    // y_tab = rn @ Wrd + b           [256,1024]
    gemm128<<<dim3(DOUT/128, KK/128), 256>>>((const float*)prn, Wrd_w, Wrd_b,
                                             (float*)pytab, KK, DOUT, DM, 1.f, 0);

    // gather + one-hot scatter
    assemble_k<<<RR, 256>>>(y, modes, writeModes);
}

// round 5
// speedup vs baseline: 1.0013x; 1.0000x over previous
#include <cuda_runtime.h>
#include <math.h>

// ---------------- problem dims ----------------
#define Bb   8
#define Ss   2048
#define RR   (Bb*Ss)       // 16384 rows
#define DIN  1024
#define HH   2048
#define KK   256
#define DM   512
#define DOUT 1024
#define BANKN 4096

// ---------------- device scratch (static, allowed) ----------------
__device__ float    d_h[(size_t)RR*HH];        // 134 MB
__device__ float    d_logits[(size_t)RR*KK];   // 16.8 MB
__device__ int      d_a0[RR];
__device__ float    d_m0[RR];
__device__ unsigned d_keep[(size_t)RR*8];      // 256-bit keep masks
__device__ int      d_mode[RR];
__device__ float    d_knT[(size_t)DM*BANKN];   // normalized bank keys, transposed [DM,BANK]
__device__ float    d_qn[KK*DM];               // normalized M rows
__device__ float    d_scores[(size_t)KK*BANKN];// scores / attn (in place)
__device__ float    d_part[8*KK*DM];           // split-K partials
__device__ float    d_bankt[KK*DM];            // bank table
__device__ float    d_rn[KK*DM];               // rms-normed table
__device__ float    d_ytab[KK*DOUT];           // final per-mode output rows

// ---------------- packed f32x2 helpers ----------------
__device__ __forceinline__ unsigned long long pack2f(float lo, float hi){
    unsigned long long r; asm("mov.b64 %0, {%1,%2};" : "=l"(r) : "f"(lo), "f"(hi)); return r;
}
__device__ __forceinline__ void unpack2f(unsigned long long v, float& lo, float& hi){
    asm("mov.b64 {%0,%1}, %2;" : "=f"(lo), "=f"(hi) : "l"(v));
}
__device__ __forceinline__ void ffma2(unsigned long long& d, unsigned long long a, unsigned long long b){
    asm("fma.rn.f32x2 %0, %1, %2, %0;" : "+l"(d) : "l"(a), "l"(b));
}

// ---------------- 128x128x16 fp32 GEMM (dual-issue f32x2 inner loop) ----------------
// C[M,N] = alpha*(A[M,K] @ B[K,N]) + bias[N], optional relu.
// gridDim.z>1 => split-K: writes raw partials to C + z*M*N (no alpha/bias/relu).
__global__ void __launch_bounds__(256, 2) gemm128(
    const float* __restrict__ A, const float* __restrict__ B,
    const float* __restrict__ bias, float* __restrict__ C,
    int M, int N, int Kd, float alpha, int doRelu)
{
    __shared__ float As[16][128];
    __shared__ float Bs[16][128];
    const int tid = threadIdx.x;
    const int bx = blockIdx.x, by = blockIdx.y;
    const int nz = gridDim.z;
    const int Kper = Kd / nz;
    const int kBase = blockIdx.z * Kper;
    const bool partial = (nz > 1);
    if (partial) C += (size_t)blockIdx.z * (size_t)M * N;

    const int aRow = tid >> 2;            // 0..63
    const int aCol = (tid & 3) << 2;      // 0,4,8,12
    const int bRow = tid >> 5;            // 0..7
    const int bCol = (tid & 31) << 2;     // 0..124
    const int tx = tid & 15, ty = tid >> 4;

    unsigned long long acc[4][8];
#pragma unroll
    for (int i = 0; i < 4; i++)
#pragma unroll
        for (int j = 0; j < 8; j++) acc[i][j] = 0ull;

    const float* Abase = A + (size_t)(by*128)*Kd + kBase;
    const float* Bbase = B + (size_t)kBase*N + bx*128;

    for (int k0 = 0; k0 < Kper; k0 += 16) {
#pragma unroll
        for (int i = 0; i < 2; i++) {
            int r = aRow + i*64;
            float4 v = *(const float4*)(Abase + (size_t)r*Kd + k0 + aCol);
            As[aCol+0][r] = v.x; As[aCol+1][r] = v.y;
            As[aCol+2][r] = v.z; As[aCol+3][r] = v.w;
        }
#pragma unroll
        for (int i = 0; i < 2; i++) {
            int r = bRow + i*8;
            *(float4*)&Bs[r][bCol] = *(const float4*)(Bbase + (size_t)(k0+r)*N + bCol);
        }
        __syncthreads();
#pragma unroll
        for (int kk = 0; kk < 16; kk++) {
            float4 av0 = *(const float4*)&As[kk][ty*8];
            float4 av1 = *(const float4*)&As[kk][ty*8+4];
            float4 bv0 = *(const float4*)&Bs[kk][tx*8];
            float4 bv1 = *(const float4*)&Bs[kk][tx*8+4];
            unsigned long long a2[4] = {
                pack2f(av0.x, av0.y), pack2f(av0.z, av0.w),
                pack2f(av1.x, av1.y), pack2f(av1.z, av1.w)};
            float bf[8] = {bv0.x,bv0.y,bv0.z,bv0.w,bv1.x,bv1.y,bv1.z,bv1.w};
#pragma unroll
            for (int j = 0; j < 8; j++) {
                unsigned long long bd = pack2f(bf[j], bf[j]);
#pragma unroll
                for (int i = 0; i < 4; i++) ffma2(acc[i][j], a2[i], bd);
            }
        }
        __syncthreads();
    }

    float out[8][8];
#pragma unroll
    for (int i2 = 0; i2 < 4; i2++)
#pragma unroll
        for (int j = 0; j < 8; j++)
            unpack2f(acc[i2][j], out[2*i2][j], out[2*i2+1][j]);

    float bl[8];
#pragma unroll
    for (int j = 0; j < 8; j++) bl[j] = 0.f;
    if (bias != nullptr && !partial) {
#pragma unroll
        for (int j = 0; j < 8; j++) bl[j] = bias[bx*128 + tx*8 + j];
    }

#pragma unroll
    for (int i = 0; i < 8; i++) {
        int row = by*128 + ty*8 + i;
        float* Crow = C + (size_t)row*N + bx*128 + tx*8;
        float vals[8];
#pragma unroll
        for (int j = 0; j < 8; j++) {
            float v = out[i][j];
            if (!partial) {
                v = v * alpha + bl[j];
                if (doRelu) v = fmaxf(v, 0.f);
            }
            vals[j] = v;
        }
        *(float4*)(Crow + 0) = make_float4(vals[0], vals[1], vals[2], vals[3]);
        *(float4*)(Crow + 4) = make_float4(vals[4], vals[5], vals[6], vals[7]);
    }
}

// ---------------- per-row argmax + keep-mask (parallel part of the scan) ----------------
__global__ void argmax_keep_k()
{
    int row = blockIdx.x * 8 + threadIdx.y;
    int lane = threadIdx.x;
    const float* lg = d_logits + (size_t)row * KK;
    float v[8];
    float best = -3.4e38f; int bi = 0;
#pragma unroll
    for (int t = 0; t < 8; t++) {
        int id = lane + t*32;
        v[t] = lg[id];
        if (v[t] > best) { best = v[t]; bi = id; }  // ascending id: strict > keeps smallest
    }
#pragma unroll
    for (int off = 16; off > 0; off >>= 1) {
        float ov = __shfl_down_sync(0xffffffffu, best, off);
        int   oi = __shfl_down_sync(0xffffffffu, bi,   off);
        if (ov > best || (ov == best && oi < bi)) { best = ov; bi = oi; }
    }
    best = __shfl_sync(0xffffffffu, best, 0);
    bi   = __shfl_sync(0xffffffffu, bi,   0);
    if (lane == 0) { d_a0[row] = bi; d_m0[row] = best; }
#pragma unroll
    for (int t = 0; t < 8; t++) {
        int id = lane + t*32;
        float adj = v[t] + 0.1f;
        bool k = (adj > best) || (adj == best && id < bi) || (id == bi);
        unsigned bw = __ballot_sync(0xffffffffu, k);
        if (lane == t) d_keep[(size_t)row*8 + t] = bw;
    }
}

// ---------------- sequential scan, O(1)/step from smem ----------------
extern __shared__ unsigned s_scan[];
__global__ void mode_scan_k(const float* __restrict__ prev_mode)
{
    int b = blockIdx.x;
    unsigned* masks = s_scan;                 // Ss*8 words
    int* a0s = (int*)(s_scan + Ss*8);         // Ss ints
    __shared__ int s_init;
    int tid = threadIdx.x;
    for (int i = tid; i < Ss*8; i += blockDim.x)
        masks[i] = d_keep[(size_t)b*Ss*8 + i];
    for (int i = tid; i < Ss; i += blockDim.x)
        a0s[i] = d_a0[b*Ss + i];
    if (tid < KK && prev_mode[b*KK + tid] > 0.5f) s_init = tid;
    __syncthreads();
    if (tid == 0) {
        int prev = s_init;
        int* outp = d_mode + b*Ss;
        for (int s = 0; s < Ss; s++) {
            unsigned w = masks[s*8 + (prev >> 5)];
            int m = ((w >> (prev & 31)) & 1u) ? prev : a0s[s];
            outp[s] = m;
            prev = m;
        }
    }
}

// ---------------- l2-normalize rows (optionally transposed output) ----------------
__global__ void l2norm_k(const float* __restrict__ in, float* __restrict__ out,
                         int nrows, int transpose)
{
    int row = blockIdx.x * 8 + threadIdx.y;
    if (row >= nrows) return;
    int lane = threadIdx.x;
    const float* p = in + (size_t)row * DM;
    float v[16]; float ss = 0.f;
#pragma unroll
    for (int t = 0; t < 16; t++) { v[t] = p[lane + t*32]; ss += v[t]*v[t]; }
#pragma unroll
    for (int off = 16; off > 0; off >>= 1) ss += __shfl_xor_sync(0xffffffffu, ss, off);
    float rn = 1.f / fmaxf(sqrtf(ss), 1e-12f);
    if (transpose) {
#pragma unroll
        for (int t = 0; t < 16; t++)
            out[(size_t)(lane + t*32) * BANKN + row] = v[t] * rn;
    } else {
#pragma unroll
        for (int t = 0; t < 16; t++)
            out[(size_t)row * DM + lane + t*32] = v[t] * rn;
    }
}

// ---------------- masked softmax over bank slots (in place on d_scores) ----------------
__global__ void softmax_k(const float* __restrict__ used)
{
    int row = blockIdx.x;
    float* s = d_scores + (size_t)row * BANKN;
    int tid = threadIdx.x;  // 256
    __shared__ float red[256];
    float v[16];
    float mx = -3.4e38f;
#pragma unroll
    for (int t = 0; t < 16; t++) {
        int c = tid + t*256;
        float x = s[c];
        x = (used[c] > 0.5f) ? x : -1e30f;
        v[t] = x; mx = fmaxf(mx, x);
    }
    red[tid] = mx; __syncthreads();
    for (int o = 128; o > 0; o >>= 1) { if (tid < o) red[tid] = fmaxf(red[tid], red[tid+o]); __syncthreads(); }
    mx = red[0]; __syncthreads();
    float sum = 0.f;
#pragma unroll
    for (int t = 0; t < 16; t++) { v[t] = expf(v[t] - mx); sum += v[t]; }
    red[tid] = sum; __syncthreads();
    for (int o = 128; o > 0; o >>= 1) { if (tid < o) red[tid] += red[tid+o]; __syncthreads(); }
    float inv = 1.f / red[0];
#pragma unroll
    for (int t = 0; t < 16; t++) s[tid + t*256] = v[t] * inv;
}

// ---------------- reduce split-K partials for the bank table ----------------
__global__ void reduce_bank_k()
{
    int i = blockIdx.x * 256 + threadIdx.x;
    float s = 0.f;
#pragma unroll
    for (int z = 0; z < 8; z++) s += d_part[(size_t)z*KK*DM + i];
    d_bankt[i] = s;
}

// ---------------- r = M[k]+bank[k]; rms-norm with g ----------------
__global__ void rms_k(const float* __restrict__ Mw, const float* __restrict__ g)
{
    int k = blockIdx.x;
    int tid = threadIdx.x;  // 128
    __shared__ float red[128];
    float r[4]; float ss = 0.f;
#pragma unroll
    for (int t = 0; t < 4; t++) {
        int c = tid + t*128;
        r[t] = Mw[(size_t)k*DM + c] + d_bankt[(size_t)k*DM + c];
        ss += r[t]*r[t];
    }
    red[tid] = ss; __syncthreads();
    for (int o = 64; o > 0; o >>= 1) { if (tid < o) red[tid] += red[tid+o]; __syncthreads(); }
    float mean = red[0] / (float)DM;
    float sc = 1.f / sqrtf(mean + 1e-6f);
#pragma unroll
    for (int t = 0; t < 4; t++) {
        int c = tid + t*128;
        d_rn[(size_t)k*DM + c] = r[t] * g[c] * sc;
    }
}

// ---------------- gather y rows + scatter one-hot modes ----------------
__global__ void assemble_k(float* __restrict__ y, float* __restrict__ modes, int writeModes)
{
    int row = blockIdx.x;
    int t = threadIdx.x;  // 256
    int m = d_mode[row];
    float4 v = ((const float4*)(d_ytab + (size_t)m * DOUT))[t];
    ((float4*)(y + (size_t)row * DOUT))[t] = v;
    if (writeModes)
        modes[(size_t)row * KK + t] = (t == m) ? 1.f : 0.f;
}

// ---------------- launch ----------------
extern "C" void kernel_launch(void* const* d_in, const int* in_sizes, int n_in,
                              void* d_out, int out_size)
{
    const float* x     = (const float*)d_in[0];
    const float* prevm = (const float*)d_in[1];
    const float* Wtr_w = (const float*)d_in[2];
    const float* Wtr_b = (const float*)d_in[3];
    const float* Wms_w = (const float*)d_in[4];
    const float* Wms_b = (const float*)d_in[5];
    const float* Mw    = (const float*)d_in[6];
    const float* g     = (const float*)d_in[7];
    const float* Wrd_w = (const float*)d_in[8];
    const float* Wrd_b = (const float*)d_in[9];
    const float* bkeys = (const float*)d_in[10];
    const float* bvals = (const float*)d_in[11];
    const float* bused = (const float*)d_in[12];

    float* y = (float*)d_out;
    int writeModes = (out_size >= (int)((size_t)RR*DOUT + (size_t)RR*KK)) ? 1 : 0;
    float* modes = y + (size_t)RR * DOUT;

    void *ph, *plog, *pknT, *pqn, *pscores, *ppart, *prn, *pytab;
    cudaGetSymbolAddress(&ph, d_h);
    cudaGetSymbolAddress(&plog, d_logits);
    cudaGetSymbolAddress(&pknT, d_knT);
    cudaGetSymbolAddress(&pqn, d_qn);
    cudaGetSymbolAddress(&pscores, d_scores);
    cudaGetSymbolAddress(&ppart, d_part);
    cudaGetSymbolAddress(&prn, d_rn);
    cudaGetSymbolAddress(&pytab, d_ytab);

    cudaFuncSetAttribute(mode_scan_k, cudaFuncAttributeMaxDynamicSharedMemorySize, 73728);

    // GEMM1: h = relu(x @ Wtr + b)   [16384,2048]
    gemm128<<<dim3(HH/128, RR/128), 256>>>(x, Wtr_w, Wtr_b, (float*)ph, RR, HH, DIN, 1.f, 1);
    // GEMM2: logits = h @ Wms + b    [16384,256]
    gemm128<<<dim3(KK/128, RR/128), 256>>>((const float*)ph, Wms_w, Wms_b, (float*)plog, RR, KK, HH, 1.f, 0);
    // per-row argmax + keep masks
    argmax_keep_k<<<RR/8, dim3(32,8)>>>();
    // sequential mode scan (8 independent batch chains)
    mode_scan_k<<<Bb, 256, 73728>>>(prevm);

    // --- mode table construction (independent of scan, tiny) ---
    l2norm_k<<<BANKN/8, dim3(32,8)>>>(bkeys, (float*)pknT, BANKN, 1);
    l2norm_k<<<KK/8,    dim3(32,8)>>>(Mw,    (float*)pqn,  KK,    0);
    // scores = 4 * qn @ knT          [256,4096]
    gemm128<<<dim3(BANKN/128, KK/128), 256>>>((const float*)pqn, (const float*)pknT, nullptr,
                                              (float*)pscores, KK, BANKN, DM, 4.0f, 0);
    softmax_k<<<KK, 256>>>(bused);
    // bank = attn @ bank_vals        [256,512]  (split-K 8)
    gemm128<<<dim3(DM/128, KK/128, 8), 256>>>((const float*)pscores, bvals, nullptr,
                                              (float*)ppart, KK, DM, BANKN, 1.f, 0);
    reduce_bank_k<<<(KK*DM)/256, 256>>>();
    rms_k<<<KK, 128>>>(Mw, g);
    // y_tab = rn @ Wrd + b           [256,1024]
    gemm128<<<dim3(DOUT/128, KK/128), 256>>>((const float*)prn, Wrd_w, Wrd_b,
                                             (float*)pytab, KK, DOUT, DM, 1.f, 0);

    // gather + one-hot scatter
    assemble_k<<<RR, 256>>>(y, modes, writeModes);
}